// round 2
// baseline (speedup 1.0000x reference)
#include <cuda_runtime.h>
#include <cuda_bf16.h>

// CumulativeLayerNorm: B=8, K=8192, H=512, fp32.
// Single-read design: per-(batch, 32-step chunk) block stages its 64KB tile in
// smem, computes per-step sum/sqsum, warp-scan over steps, deterministic
// full-prefix lookback across chunks, then normalizes from smem.

#define Hh 512
#define Kk 8192
#define TK 32
#define NC (Kk / TK)        // 256 chunks per batch
#define THREADS 256
#define NWARPS (THREADS / 32)
#define SPW (TK / NWARPS)   // 4 steps per warp
#define MAXB 16

__device__ int          g_flag[MAXB * NC];
__device__ float        g_asum[MAXB * NC];
__device__ float        g_asq [MAXB * NC];
__device__ unsigned int g_ticket;

__global__ void cln_init_kernel(int nflags) {
    int i = blockIdx.x * blockDim.x + threadIdx.x;
    if (i == 0) g_ticket = 0u;
    for (int j = i; j < nflags; j += gridDim.x * blockDim.x) g_flag[j] = 0;
}

__global__ void __launch_bounds__(THREADS)
cln_kernel(const float* __restrict__ in,
           const float* __restrict__ gamma,
           const float* __restrict__ beta,
           float* __restrict__ out)
{
    extern __shared__ float4 s_data[];           // TK * (H/4) float4 = 64 KB
    __shared__ float s_sum[TK], s_sq[TK], s_mean[TK], s_istd[TK];
    __shared__ unsigned s_ticket;

    const int tid  = threadIdx.x;
    const int warp = tid >> 5;
    const int lane = tid & 31;

    if (tid == 0) s_ticket = atomicAdd(&g_ticket, 1u);

    // gamma / beta into registers (same lanes used in phase C)
    float4 g4[4], b4[4];
    {
        const float4* gp = (const float4*)gamma;
        const float4* bp = (const float4*)beta;
#pragma unroll
        for (int j = 0; j < 4; ++j) {
            g4[j] = gp[j * 32 + lane];
            b4[j] = bp[j * 32 + lane];
        }
    }

    __syncthreads();
    const unsigned ticket = s_ticket;
    const int b  = (int)(ticket / NC);
    const int c  = (int)(ticket % NC);
    const int k0 = c * TK;

    const float4* inp  = (const float4*)(in  + ((size_t)b * Kk + k0) * Hh);
    float4*       outp = (float4*)      (out + ((size_t)b * Kk + k0) * Hh);

    // ---- Phase A: load tile once, per-step sum / sqsum ----
#pragma unroll
    for (int i = 0; i < SPW; ++i) {
        const int s = warp * SPW + i;
        float sum = 0.f, sq = 0.f;
#pragma unroll
        for (int j = 0; j < 4; ++j) {
            float4 v = inp[s * (Hh / 4) + j * 32 + lane];
            s_data[s * (Hh / 4) + j * 32 + lane] = v;
            sum += v.x + v.y + v.z + v.w;
            sq  += v.x * v.x + v.y * v.y + v.z * v.z + v.w * v.w;
        }
#pragma unroll
        for (int o = 16; o > 0; o >>= 1) {
            sum += __shfl_xor_sync(0xffffffffu, sum, o);
            sq  += __shfl_xor_sync(0xffffffffu, sq,  o);
        }
        if (lane == 0) { s_sum[s] = sum; s_sq[s] = sq; }
    }
    __syncthreads();

    // ---- Phase B: warp 0 scans steps + cross-chunk prefix ----
    if (warp == 0) {
        float v1 = s_sum[lane], v2 = s_sq[lane];
        // inclusive scan over 32 steps
#pragma unroll
        for (int o = 1; o < 32; o <<= 1) {
            float t1 = __shfl_up_sync(0xffffffffu, v1, o);
            float t2 = __shfl_up_sync(0xffffffffu, v2, o);
            if (lane >= o) { v1 += t1; v2 += t2; }
        }
        const float a1 = __shfl_sync(0xffffffffu, v1, 31);
        const float a2 = __shfl_sync(0xffffffffu, v2, 31);

        // publish this chunk's aggregate (release: fence then flag)
        if (lane == 0) {
            g_asum[b * NC + c] = a1;
            g_asq [b * NC + c] = a2;
            __threadfence();
            atomicExch(&g_flag[b * NC + c], 1);
        }

        // deterministic full lookback: sum ALL predecessor aggregates in a
        // fixed grouping (32 at a time, descending), so replayed launches
        // produce bit-identical results. Deadlock-free: every flag waited on
        // belongs to a block that already acquired a smaller ticket (i.e. has
        // started) and publishes before it spins.
        float p1 = 0.f, p2 = 0.f;
        const int nrounds = (c + 31) >> 5;
        for (int r = 0; r < nrounds; ++r) {
            const int p = c - 1 - (r * 32 + lane);
            float x1 = 0.f, x2 = 0.f;
            if (p >= 0) {
                while (*(volatile int*)&g_flag[b * NC + p] == 0) {
                    __nanosleep(40);
                }
                __threadfence();
                x1 = *(volatile float*)&g_asum[b * NC + p];
                x2 = *(volatile float*)&g_asq [b * NC + p];
            }
            __syncwarp();
#pragma unroll
            for (int o = 16; o > 0; o >>= 1) {
                x1 += __shfl_xor_sync(0xffffffffu, x1, o);
                x2 += __shfl_xor_sync(0xffffffffu, x2, o);
            }
            p1 += x1; p2 += x2;
        }

        const float cs  = p1 + v1;
        const float cq  = p2 + v2;
        const float cnt = (float)(k0 + lane + 1) * (float)Hh;
        const float mean = cs / cnt;
        const float var  = cq / cnt - mean * mean;
        s_mean[lane] = mean;
        s_istd[lane] = rsqrtf(var + 1e-8f);
    }
    __syncthreads();

    // ---- Phase C: normalize out of smem, streaming stores ----
#pragma unroll
    for (int i = 0; i < SPW; ++i) {
        const int s = warp * SPW + i;
        const float mean = s_mean[s];
        const float istd = s_istd[s];
#pragma unroll
        for (int j = 0; j < 4; ++j) {
            float4 v = s_data[s * (Hh / 4) + j * 32 + lane];
            float4 r;
            r.x = g4[j].x * (v.x - mean) * istd + b4[j].x;
            r.y = g4[j].y * (v.y - mean) * istd + b4[j].y;
            r.z = g4[j].z * (v.z - mean) * istd + b4[j].z;
            r.w = g4[j].w * (v.w - mean) * istd + b4[j].w;
            __stcs(&outp[s * (Hh / 4) + j * 32 + lane], r);
        }
    }
}

extern "C" void kernel_launch(void* const* d_in, const int* in_sizes, int n_in,
                              void* d_out, int out_size)
{
    const float* in    = (const float*)d_in[0];
    const float* gamma = (const float*)d_in[1];
    const float* beta  = (const float*)d_in[2];
    float*       out   = (float*)d_out;

    int B = in_sizes[0] / (Kk * Hh);   // 8 for this problem
    if (B > MAXB) B = MAXB;
    const int smem = TK * Hh * (int)sizeof(float);  // 65536

    cudaFuncSetAttribute(cln_kernel,
                         cudaFuncAttributeMaxDynamicSharedMemorySize, smem);

    cln_init_kernel<<<8, 256>>>(B * NC);
    cln_kernel<<<B * NC, THREADS, smem>>>(in, gamma, beta, out);
}